// round 1
// baseline (speedup 1.0000x reference)
#include <cuda_runtime.h>
#include <cstdint>

#define H       512
#define HEADS   8
#define DK      64
#define NCLASS  4
#define VOCAB   5000
#define LW      32
#define NLEAF   20000
#define NPAR    20000
#define NTOT    40000
#define DEG     4
#define NLAYER  5
#define HP      (H + 8)      // padded pitch for bank-conflict relief
#define NB_RED  125
#define RED_CHUNK 160        // 125*160 = 20000

// ---- scratch (static device globals; no allocation at runtime) ----
__device__ float g_nodeh[(size_t)NTOT * H];     // 82 MB: h for every node
__device__ float g_xepar[(size_t)NPAR * H];     // xe for parents
__device__ float g_EbuT[(size_t)VOCAB * H];     // transposed embedding
__device__ int   g_flags[NPAR];                 // parent-ready flags
__device__ float g_pmax[NB_RED * H];            // partial max

// ------------------------------------------------------------------
__global__ void k_zero_flags() {
    int i = blockIdx.x * blockDim.x + threadIdx.x;
    if (i < NPAR) g_flags[i] = 0;
}

// E_bu [H, VOCAB] -> g_EbuT [VOCAB, H]
__global__ void k_transpose(const float* __restrict__ E) {
    __shared__ float t[32][33];
    int x = blockIdx.x * 32 + threadIdx.x;          // vocab
    int y0 = blockIdx.y * 32;                        // h
#pragma unroll
    for (int j = 0; j < 32; j += 8) {
        int y = y0 + threadIdx.y + j;
        t[threadIdx.y + j][threadIdx.x] = (x < VOCAB) ? E[(size_t)y * VOCAB + x] : 0.f;
    }
    __syncthreads();
    int xo = blockIdx.y * 32 + threadIdx.x;          // h
    int yo0 = blockIdx.x * 32;                       // vocab
#pragma unroll
    for (int j = 0; j < 32; j += 8) {
        int yo = yo0 + threadIdx.y + j;
        if (yo < VOCAB) g_EbuT[(size_t)yo * H + xo] = t[threadIdx.x][threadIdx.y + j];
    }
}

// xe[n] = sum_l w[n,l] * EbuT[idx[n,l], :]; leaves -> node_h, parents -> xepar
__global__ void k_embed(const float* __restrict__ xw, const int* __restrict__ xi) {
    int n = blockIdx.x;
    int tid = threadIdx.x;                  // 128 threads, float4 each
    __shared__ float s_w[LW];
    __shared__ int   s_i[LW];
    if (tid < LW) { s_w[tid] = xw[n * LW + tid]; s_i[tid] = xi[n * LW + tid]; }
    __syncthreads();
    float4 acc = make_float4(0.f, 0.f, 0.f, 0.f);
#pragma unroll 8
    for (int l = 0; l < LW; l++) {
        const float4* row = (const float4*)(g_EbuT + (size_t)s_i[l] * H);
        float4 e = row[tid];
        float w = s_w[l];
        acc.x += w * e.x; acc.y += w * e.y; acc.z += w * e.z; acc.w += w * e.w;
    }
    float4* dst = (n < NLEAF) ? (float4*)(g_nodeh + (size_t)n * H)
                              : (float4*)(g_xepar + (size_t)(n - NLEAF) * H);
    dst[tid] = acc;
}

__device__ __forceinline__ float sigmoidf_(float x) { return 1.f / (1.f + __expf(-x)); }

// Persistent dataflow kernel over parents.
__global__ void __launch_bounds__(512, 2) k_tree(
    const int* __restrict__ tree,
    const float* __restrict__ Wz, const float* __restrict__ Uz, const float* __restrict__ bz,
    const float* __restrict__ Wr, const float* __restrict__ Ur, const float* __restrict__ br,
    const float* __restrict__ Wh, const float* __restrict__ Uh, const float* __restrict__ bh)
{
    __shared__ float s_h[2][DEG][HP];
    __shared__ float s_xe[H];
    __shared__ float s_mem[H];
    __shared__ float s_mr[H];
    __shared__ float s_sc[HEADS][DEG][DEG];
    __shared__ float s_p[HEADS][DEG][DEG];
    __shared__ int   s_child[DEG];

    int tid = threadIdx.x;

    for (int p = blockIdx.x; p < NPAR; p += gridDim.x) {
        if (tid < DEG) s_child[tid] = tree[p * DEG + tid];
        __syncthreads();

        // wait for parent-children readiness (ids strictly < NLEAF+p => no cycles)
        if (tid < DEG) {
            int c = s_child[tid];
            if (c >= NLEAF) {
                while (atomicAdd(&g_flags[c - NLEAF], 0) == 0) __nanosleep(100);
                __threadfence();   // acquire
            }
        }
        __syncthreads();

        // gather children h (L2 loads; L1 may be stale across SMs)
#pragma unroll
        for (int k = 0; k < DEG; k++) {
            int c = s_child[k];
            s_h[0][k][tid] = (c > -1) ? __ldcg(g_nodeh + (size_t)c * H + tid) : 0.f;
        }
        s_xe[tid] = g_xepar[(size_t)p * H + tid];
        __syncthreads();

        // 5 layers of 4-token / 8-head self-attention (q=k=v=h)
        int cur = 0;
        for (int layer = 0; layer < NLAYER; layer++) {
            if (tid < HEADS * DEG * DEG) {
                int head = tid >> 4, q = (tid >> 2) & 3, kk = tid & 3;
                const float* hq = &s_h[cur][q][head * DK];
                const float* hk = &s_h[cur][kk][head * DK];
                float s = 0.f;
#pragma unroll
                for (int d = 0; d < DK; d++) s += hq[d] * hk[d];
                s *= 0.125f;                        // 1/sqrt(64)
                if (s_child[kk] <= -1) s = -1e9f;   // key mask (matches reference)
                s_sc[head][q][kk] = s;
            }
            __syncthreads();
            if (tid < HEADS * DEG) {
                int head = tid >> 2, q = tid & 3;
                float m = s_sc[head][q][0];
#pragma unroll
                for (int kk = 1; kk < DEG; kk++) m = fmaxf(m, s_sc[head][q][kk]);
                float e[DEG]; float sum = 0.f;
#pragma unroll
                for (int kk = 0; kk < DEG; kk++) { e[kk] = __expf(s_sc[head][q][kk] - m); sum += e[kk]; }
                float inv = 1.f / sum;
#pragma unroll
                for (int kk = 0; kk < DEG; kk++) s_p[head][q][kk] = e[kk] * inv;
            }
            __syncthreads();
            {
                int head = tid >> 6, d = tid & 63;
                int col = head * DK + d;
                float v0 = s_h[cur][0][col], v1 = s_h[cur][1][col];
                float v2 = s_h[cur][2][col], v3 = s_h[cur][3][col];
#pragma unroll
                for (int q = 0; q < DEG; q++) {
                    s_h[cur ^ 1][q][col] = s_p[head][q][0] * v0 + s_p[head][q][1] * v1
                                         + s_p[head][q][2] * v2 + s_p[head][q][3] * v3;
                }
            }
            __syncthreads();
            cur ^= 1;
        }

        // memory = masked mean over children
        {
            int cnt = 0;
#pragma unroll
            for (int k = 0; k < DEG; k++) cnt += (s_child[k] > -1);
            float denom = (float)max(cnt, 1);
            float m = 0.f;
#pragma unroll
            for (int k = 0; k < DEG; k++) if (s_child[k] > -1) m += s_h[cur][k][tid];
            s_mem[tid] = m / denom;
        }
        __syncthreads();

        // GRU: stage 1 (z, r, Wh·xe), fp32 matvecs, each thread owns one output dim
        float az = bz[tid], ar = br[tid], ac = bh[tid];
        {
            const float4* wz = (const float4*)(Wz + (size_t)tid * H);
            const float4* uz = (const float4*)(Uz + (size_t)tid * H);
            const float4* wr = (const float4*)(Wr + (size_t)tid * H);
            const float4* ur = (const float4*)(Ur + (size_t)tid * H);
            const float4* wh = (const float4*)(Wh + (size_t)tid * H);
            const float4* xv = (const float4*)s_xe;
            const float4* mv = (const float4*)s_mem;
#pragma unroll 2
            for (int j = 0; j < H / 4; j++) {
                float4 x = xv[j], m = mv[j];
                float4 a = wz[j]; az += a.x*x.x + a.y*x.y + a.z*x.z + a.w*x.w;
                float4 b = uz[j]; az += b.x*m.x + b.y*m.y + b.z*m.z + b.w*m.w;
                float4 cR = wr[j]; ar += cR.x*x.x + cR.y*x.y + cR.z*x.z + cR.w*x.w;
                float4 dR = ur[j]; ar += dR.x*m.x + dR.y*m.y + dR.z*m.z + dR.w*m.w;
                float4 eH = wh[j]; ac += eH.x*x.x + eH.y*x.y + eH.z*x.z + eH.w*x.w;
            }
        }
        float z = sigmoidf_(az), r = sigmoidf_(ar);
        s_mr[tid] = s_mem[tid] * r;
        __syncthreads();
        // stage 2: Uh·(mem*r)
        {
            const float4* uh = (const float4*)(Uh + (size_t)tid * H);
            const float4* mr = (const float4*)s_mr;
#pragma unroll 2
            for (int j = 0; j < H / 4; j++) {
                float4 a = uh[j], b = mr[j];
                ac += a.x*b.x + a.y*b.y + a.z*b.z + a.w*b.w;
            }
        }
        float c = tanhf(ac);
        float ph = z * s_mem[tid] + (1.f - z) * c;
        __stcg(g_nodeh + (size_t)(NLEAF + p) * H + tid, ph);
        __syncthreads();
        if (tid == 0) {
            __threadfence();            // release
            atomicExch(&g_flags[p], 1);
        }
        // s_child/s_xe overwritten next iter only after the barrier above
    }
}

// partial column-max over parents
__global__ void k_redmax() {
    int tid = threadIdx.x;
    int b = blockIdx.x;
    const float* base = g_nodeh + (size_t)NLEAF * H;
    float m = -3.4e38f;
    for (int p = b * RED_CHUNK; p < (b + 1) * RED_CHUNK; p++)
        m = fmaxf(m, base[(size_t)p * H + tid]);
    g_pmax[b * H + tid] = m;
}

__global__ void k_final(const float* __restrict__ Wo, const float* __restrict__ bo,
                        float* __restrict__ out) {
    __shared__ float s_f[H];
    __shared__ float s_logit[NCLASS];
    int tid = threadIdx.x;  // 512
    float m = g_pmax[tid];
    for (int b = 1; b < NB_RED; b++) m = fmaxf(m, g_pmax[b * H + tid]);
    s_f[tid] = m;
    __syncthreads();
    int w = tid >> 5, lane = tid & 31;
    if (w < NCLASS) {
        float acc = 0.f;
        for (int j = lane; j < H; j += 32) acc += Wo[w * H + j] * s_f[j];
#pragma unroll
        for (int off = 16; off; off >>= 1) acc += __shfl_down_sync(0xffffffffu, acc, off);
        if (lane == 0) s_logit[w] = acc + bo[w];
    }
    __syncthreads();
    if (tid == 0) {
        float mx = s_logit[0];
        for (int i = 1; i < NCLASS; i++) mx = fmaxf(mx, s_logit[i]);
        float e[NCLASS], s = 0.f;
        for (int i = 0; i < NCLASS; i++) { e[i] = __expf(s_logit[i] - mx); s += e[i]; }
        for (int i = 0; i < NCLASS; i++) out[i] = e[i] / s;
    }
}

extern "C" void kernel_launch(void* const* d_in, const int* in_sizes, int n_in,
                              void* d_out, int out_size) {
    const float* x_word  = (const float*)d_in[0];
    const int*   x_index = (const int*)  d_in[1];
    const int*   tree    = (const int*)  d_in[2];
    const float* E_bu    = (const float*)d_in[3];
    const float* W_z = (const float*)d_in[4];
    const float* U_z = (const float*)d_in[5];
    const float* b_z = (const float*)d_in[6];
    const float* W_r = (const float*)d_in[7];
    const float* U_r = (const float*)d_in[8];
    const float* b_r = (const float*)d_in[9];
    const float* W_h = (const float*)d_in[10];
    const float* U_h = (const float*)d_in[11];
    const float* b_h = (const float*)d_in[12];
    const float* W_out = (const float*)d_in[13];
    const float* b_out = (const float*)d_in[14];
    float* out = (float*)d_out;

    // guaranteed-co-resident persistent grid (computed once; pure constant)
    static int nb_tree = 0;
    if (nb_tree == 0) {
        int dev = 0; cudaGetDevice(&dev);
        int nsm = 0; cudaDeviceGetAttribute(&nsm, cudaDevAttrMultiProcessorCount, dev);
        int perSM = 0;
        cudaOccupancyMaxActiveBlocksPerMultiprocessor(&perSM, k_tree, 512, 0);
        if (perSM < 1) perSM = 1;
        long nb = (long)nsm * perSM;
        if (nb > NPAR) nb = NPAR;
        nb_tree = (int)nb;
    }

    k_zero_flags<<<(NPAR + 255) / 256, 256>>>();
    dim3 tb(32, 8);
    dim3 tg((VOCAB + 31) / 32, H / 32);
    k_transpose<<<tg, tb>>>(E_bu);
    k_embed<<<NTOT, 128>>>(x_word, x_index);
    k_tree<<<nb_tree, 512>>>(tree, W_z, U_z, b_z, W_r, U_r, b_r, W_h, U_h, b_h);
    k_redmax<<<NB_RED, H>>>();
    k_final<<<1, H>>>(W_out, b_out, out);
}